// round 1
// baseline (speedup 1.0000x reference)
#include <cuda_runtime.h>
#include <cstddef>

// Problem constants
#define NB   128          // batch
#define T    256          // sequence
#define CC   384          // embed
#define NH   6            // heads
#define HS   64           // head size
#define C4   1536         // 4*C
#define QKVN 1152         // 3*C
#define BT   32768        // NB*T

// ---------------- scratch (device globals; no allocation allowed) ----------
__device__ float g_h[BT * CC];                       // LN output (reused for LN1 and LN2)
__device__ float g_qkv[(size_t)BT * QKVN];           // q|k|v, (B*T, 1152)
__device__ float g_wei[(size_t)NB * NH * T * T];     // S^T per (b,h): [s][t], then P^T
__device__ float g_attn[BT * CC];                    // attention output, (B,T,C) head-concat
__device__ float g_x1[BT * CC];                      // x after attn sublayer
__device__ float g_u[(size_t)BT * C4];               // MLP hidden
__device__ float g_wpack[CC * QKVN];                 // packed QKV weights (C x 3C)

// ---------------- weight packing: (h,c,d)x3 -> (c, w*384 + h*64 + d) -------
__global__ void pack_kernel(const float* __restrict__ wq,
                            const float* __restrict__ wk,
                            const float* __restrict__ wv,
                            float* __restrict__ wp) {
    int idx = blockIdx.x * 256 + threadIdx.x;
    const int per = NH * CC * HS;                    // 147456
    if (idx >= 3 * per) return;
    int w = idx / per;
    int rem = idx - w * per;                          // (h*C + c)*HS + d
    int d = rem % HS;
    int hc = rem / HS;
    int c = hc % CC;
    int h = hc / CC;
    const float* src = (w == 0) ? wq : (w == 1) ? wk : wv;
    wp[(size_t)c * QKVN + w * CC + h * HS + d] = src[rem];
}

// ---------------- LayerNorm: one block (128 thr) per row --------------------
__global__ void __launch_bounds__(128)
ln_kernel(const float* __restrict__ x, const float* __restrict__ g,
          const float* __restrict__ b, float* __restrict__ out) {
    int row = blockIdx.x;
    const float* xr = x + (size_t)row * CC;
    int t = threadIdx.x;
    float v0 = xr[t], v1 = xr[t + 128], v2 = xr[t + 256];
    float s  = v0 + v1 + v2;
    float ss = v0 * v0 + v1 * v1 + v2 * v2;
    __shared__ float red[8];
    __shared__ float red2[8];
    #pragma unroll
    for (int o = 16; o > 0; o >>= 1) {
        s  += __shfl_down_sync(0xffffffffu, s, o);
        ss += __shfl_down_sync(0xffffffffu, ss, o);
    }
    int warp = t >> 5, lane = t & 31;
    if (lane == 0) { red[warp] = s; red2[warp] = ss; }
    __syncthreads();
    if (t == 0) {
        float S  = red[0] + red[1] + red[2] + red[3];
        float SS = red2[0] + red2[1] + red2[2] + red2[3];
        float mu = S * (1.0f / CC);
        float var = SS * (1.0f / CC) - mu * mu;
        red[4] = mu;
        red2[4] = rsqrtf(var + 1e-5f);
    }
    __syncthreads();
    float mu = red[4], inv = red2[4];
    float* o = out + (size_t)row * CC;
    o[t]       = (v0 - mu) * inv * g[t]       + b[t];
    o[t + 128] = (v1 - mu) * inv * g[t + 128] + b[t + 128];
    o[t + 256] = (v2 - mu) * inv * g[t + 256] + b[t + 256];
}

// ---------------- generic SGEMM: C = epi(A(MxK,row) * B(KxN,row)) -----------
// 128x128 tile, BK=8, 256 threads, 8x8 microtile split at +64.
// EPI: 0 = plain, 1 = + bias + residual, 2 = relu(+ bias)
template <int EPI>
__global__ void __launch_bounds__(256)
gemm_kernel(const float* __restrict__ A, const float* __restrict__ Bm,
            const float* __restrict__ bias, const float* __restrict__ res,
            float* __restrict__ Cout, int M, int N, int K) {
    __shared__ float As[8][128];
    __shared__ float Bs[8][128];
    int tid = threadIdx.x;
    int m0 = blockIdx.y * 128;
    int n0 = blockIdx.x * 128;
    int tx = tid & 15, ty = tid >> 4;

    float acc[8][8];
    #pragma unroll
    for (int i = 0; i < 8; i++)
        #pragma unroll
        for (int j = 0; j < 8; j++) acc[i][j] = 0.0f;

    int arow = tid >> 1;
    int akp  = (tid & 1) * 4;
    int bkr  = tid >> 5;
    int bcol = (tid & 31) * 4;

    const float* Aptr = A + (size_t)(m0 + arow) * K + akp;
    const float* Bptr = Bm + (size_t)bkr * N + n0 + bcol;

    for (int k0 = 0; k0 < K; k0 += 8) {
        float4 av = *(const float4*)(Aptr + k0);
        float4 bv = *(const float4*)(Bptr + (size_t)k0 * N);
        As[akp + 0][arow] = av.x;
        As[akp + 1][arow] = av.y;
        As[akp + 2][arow] = av.z;
        As[akp + 3][arow] = av.w;
        *(float4*)&Bs[bkr][bcol] = bv;
        __syncthreads();
        #pragma unroll
        for (int k = 0; k < 8; k++) {
            float a[8], bb[8];
            *(float4*)&a[0]  = *(const float4*)&As[k][ty * 4];
            *(float4*)&a[4]  = *(const float4*)&As[k][64 + ty * 4];
            *(float4*)&bb[0] = *(const float4*)&Bs[k][tx * 4];
            *(float4*)&bb[4] = *(const float4*)&Bs[k][64 + tx * 4];
            #pragma unroll
            for (int i = 0; i < 8; i++)
                #pragma unroll
                for (int j = 0; j < 8; j++)
                    acc[i][j] = fmaf(a[i], bb[j], acc[i][j]);
        }
        __syncthreads();
    }

    #pragma unroll
    for (int i = 0; i < 8; i++) {
        int r = m0 + ((i < 4) ? (ty * 4 + i) : (64 + ty * 4 + i - 4));
        #pragma unroll
        for (int jj = 0; jj < 2; jj++) {
            int c0 = n0 + ((jj == 0) ? (tx * 4) : (64 + tx * 4));
            float4 v;
            v.x = acc[i][jj * 4 + 0];
            v.y = acc[i][jj * 4 + 1];
            v.z = acc[i][jj * 4 + 2];
            v.w = acc[i][jj * 4 + 3];
            if (EPI == 1) {
                float4 bb = *(const float4*)(bias + c0);
                float4 rr = *(const float4*)(res + (size_t)r * N + c0);
                v.x += bb.x + rr.x; v.y += bb.y + rr.y;
                v.z += bb.z + rr.z; v.w += bb.w + rr.w;
            } else if (EPI == 2) {
                float4 bb = *(const float4*)(bias + c0);
                v.x = fmaxf(v.x + bb.x, 0.0f); v.y = fmaxf(v.y + bb.y, 0.0f);
                v.z = fmaxf(v.z + bb.z, 0.0f); v.w = fmaxf(v.w + bb.w, 0.0f);
            }
            *(float4*)(Cout + (size_t)r * N + c0) = v;
        }
    }
}

// ---------------- scores: S^T[s][t] = scale * K[s].Q[t], causal mask -------
// grid: (quad 0..3, bh 0..767). quad: s0=(quad>>1)*128, t0=(quad&1)*128.
__global__ void __launch_bounds__(256)
scores_kernel(const float* __restrict__ qkv, float* __restrict__ wei) {
    int bh = blockIdx.y;
    int b = bh / NH, h = bh % NH;
    int quad = blockIdx.x;
    int s0 = (quad >> 1) * 128;
    int t0 = (quad & 1) * 128;
    int tid = threadIdx.x;
    float* W = wei + (size_t)bh * (T * T);

    if (t0 + 127 < s0) {  // fully masked quad (s in [128,256), t in [0,128))
        for (int i = tid; i < 128 * 128; i += 256) {
            int s = i >> 7, t = i & 127;
            W[(size_t)(s0 + s) * T + t0 + t] = -1e30f;
        }
        return;
    }

    __shared__ float Ks[8][128];
    __shared__ float Qs[8][128];
    int tx = tid & 15, ty = tid >> 4;
    float acc[8][8];
    #pragma unroll
    for (int i = 0; i < 8; i++)
        #pragma unroll
        for (int j = 0; j < 8; j++) acc[i][j] = 0.0f;

    int arow = tid >> 1;
    int akp  = (tid & 1) * 4;
    const float* Kp = qkv + (size_t)(b * T + s0 + arow) * QKVN + CC + h * HS + akp;
    const float* Qp = qkv + (size_t)(b * T + t0 + arow) * QKVN + 0  + h * HS + akp;

    for (int k0 = 0; k0 < HS; k0 += 8) {
        float4 kv = *(const float4*)(Kp + k0);
        float4 qv = *(const float4*)(Qp + k0);
        Ks[akp + 0][arow] = kv.x; Ks[akp + 1][arow] = kv.y;
        Ks[akp + 2][arow] = kv.z; Ks[akp + 3][arow] = kv.w;
        Qs[akp + 0][arow] = qv.x; Qs[akp + 1][arow] = qv.y;
        Qs[akp + 2][arow] = qv.z; Qs[akp + 3][arow] = qv.w;
        __syncthreads();
        #pragma unroll
        for (int k = 0; k < 8; k++) {
            float a[8], bb[8];
            *(float4*)&a[0]  = *(const float4*)&Ks[k][ty * 4];
            *(float4*)&a[4]  = *(const float4*)&Ks[k][64 + ty * 4];
            *(float4*)&bb[0] = *(const float4*)&Qs[k][tx * 4];
            *(float4*)&bb[4] = *(const float4*)&Qs[k][64 + tx * 4];
            #pragma unroll
            for (int i = 0; i < 8; i++)
                #pragma unroll
                for (int j = 0; j < 8; j++)
                    acc[i][j] = fmaf(a[i], bb[j], acc[i][j]);
        }
        __syncthreads();
    }

    const float scale = 0.05103103630798288f;  // 384^-0.5
    #pragma unroll
    for (int i = 0; i < 8; i++) {
        int s = s0 + ((i < 4) ? (ty * 4 + i) : (64 + ty * 4 + i - 4));
        #pragma unroll
        for (int jj = 0; jj < 2; jj++) {
            int tb = t0 + ((jj == 0) ? (tx * 4) : (64 + tx * 4));
            float4 v;
            float* pv = &v.x;
            #pragma unroll
            for (int q = 0; q < 4; q++) {
                float val = acc[i][jj * 4 + q] * scale;
                pv[q] = (tb + q >= s) ? val : -1e30f;
            }
            *(float4*)(W + (size_t)s * T + tb) = v;
        }
    }
}

// ---------------- column softmax (rows of S^T): warp per row ---------------
__global__ void __launch_bounds__(256)
softmax_kernel(float* __restrict__ wei) {
    int bh = blockIdx.x;
    float* W = wei + (size_t)bh * (T * T);
    int warp = threadIdx.x >> 5, lane = threadIdx.x & 31;
    for (int r = warp; r < T; r += 8) {
        float* row = W + (size_t)r * T;
        float v[8];
        float m = -3e30f;
        #pragma unroll
        for (int j = 0; j < 8; j++) {
            v[j] = row[lane + 32 * j];
            m = fmaxf(m, v[j]);
        }
        #pragma unroll
        for (int o = 16; o > 0; o >>= 1) m = fmaxf(m, __shfl_xor_sync(0xffffffffu, m, o));
        float ssum = 0.0f;
        #pragma unroll
        for (int j = 0; j < 8; j++) {
            v[j] = __expf(v[j] - m);
            ssum += v[j];
        }
        #pragma unroll
        for (int o = 16; o > 0; o >>= 1) ssum += __shfl_xor_sync(0xffffffffu, ssum, o);
        float inv = 1.0f / ssum;
        #pragma unroll
        for (int j = 0; j < 8; j++) row[lane + 32 * j] = v[j] * inv;
    }
}

// ---------------- O[t][d] = sum_s P^T[s][t] * V[s][d]  (TN gemm) -----------
// grid: (t-tile 0..1, bh). 256 threads, microtile 8x4 (t split +-64, d 4).
__global__ void __launch_bounds__(256)
av_kernel(const float* __restrict__ qkv, const float* __restrict__ wei,
          float* __restrict__ attn) {
    int bh = blockIdx.y;
    int b = bh / NH, h = bh % NH;
    int t0 = blockIdx.x * 128;
    __shared__ float Ps[16][128];
    __shared__ float Vs[16][64];
    int tid = threadIdx.x;
    int tx = tid & 15, ty = tid >> 4;
    float acc[8][4];
    #pragma unroll
    for (int i = 0; i < 8; i++)
        #pragma unroll
        for (int j = 0; j < 4; j++) acc[i][j] = 0.0f;

    const float* W = wei + (size_t)bh * (T * T);

    for (int s0 = 0; s0 < T; s0 += 16) {
        #pragma unroll
        for (int i = 0; i < 2; i++) {
            int idx = tid + 256 * i;
            int sr = idx >> 5;
            int tc = (idx & 31) * 4;
            *(float4*)&Ps[sr][tc] = *(const float4*)(W + (size_t)(s0 + sr) * T + t0 + tc);
        }
        {
            int sr = tid >> 4;
            int dc = (tid & 15) * 4;
            *(float4*)&Vs[sr][dc] =
                *(const float4*)(qkv + (size_t)(b * T + s0 + sr) * QKVN + 2 * CC + h * HS + dc);
        }
        __syncthreads();
        #pragma unroll
        for (int k = 0; k < 16; k++) {
            float a[8], bb[4];
            *(float4*)&a[0]  = *(const float4*)&Ps[k][ty * 4];
            *(float4*)&a[4]  = *(const float4*)&Ps[k][64 + ty * 4];
            *(float4*)&bb[0] = *(const float4*)&Vs[k][tx * 4];
            #pragma unroll
            for (int i = 0; i < 8; i++)
                #pragma unroll
                for (int j = 0; j < 4; j++)
                    acc[i][j] = fmaf(a[i], bb[j], acc[i][j]);
        }
        __syncthreads();
    }

    #pragma unroll
    for (int i = 0; i < 8; i++) {
        int t = t0 + ((i < 4) ? (ty * 4 + i) : (64 + ty * 4 + i - 4));
        float4 v;
        v.x = acc[i][0]; v.y = acc[i][1]; v.z = acc[i][2]; v.w = acc[i][3];
        *(float4*)(attn + (size_t)(b * T + t) * CC + h * HS + tx * 4) = v;
    }
}

// ---------------- launch ----------------------------------------------------
extern "C" void kernel_launch(void* const* d_in, const int* in_sizes, int n_in,
                              void* d_out, int out_size) {
    (void)in_sizes; (void)n_in; (void)out_size;
    const float* x      = (const float*)d_in[0];
    const float* wq     = (const float*)d_in[1];
    const float* wk     = (const float*)d_in[2];
    const float* wv     = (const float*)d_in[3];
    const float* w_proj = (const float*)d_in[4];
    const float* b_proj = (const float*)d_in[5];
    const float* w1     = (const float*)d_in[6];
    const float* b1     = (const float*)d_in[7];
    const float* w2     = (const float*)d_in[8];
    const float* b2     = (const float*)d_in[9];
    const float* ln1_g  = (const float*)d_in[10];
    const float* ln1_b  = (const float*)d_in[11];
    const float* ln2_g  = (const float*)d_in[12];
    const float* ln2_b  = (const float*)d_in[13];
    float* out = (float*)d_out;

    void *ph, *pqkv, *pwei, *pattn, *px1, *pu, *pwp;
    cudaGetSymbolAddress(&ph,    g_h);
    cudaGetSymbolAddress(&pqkv,  g_qkv);
    cudaGetSymbolAddress(&pwei,  g_wei);
    cudaGetSymbolAddress(&pattn, g_attn);
    cudaGetSymbolAddress(&px1,   g_x1);
    cudaGetSymbolAddress(&pu,    g_u);
    cudaGetSymbolAddress(&pwp,   g_wpack);
    float* fh    = (float*)ph;
    float* fqkv  = (float*)pqkv;
    float* fwei  = (float*)pwei;
    float* fattn = (float*)pattn;
    float* fx1   = (float*)px1;
    float* fu    = (float*)pu;
    float* fwp   = (float*)pwp;

    // 1) pack QKV weights
    pack_kernel<<<(3 * NH * CC * HS + 255) / 256, 256>>>(wq, wk, wv, fwp);
    // 2) LN1
    ln_kernel<<<BT, 128>>>(x, ln1_g, ln1_b, fh);
    // 3) QKV projection: (32768 x 384) @ (384 x 1152)
    gemm_kernel<0><<<dim3(QKVN / 128, BT / 128), 256>>>(fh, fwp, nullptr, nullptr,
                                                        fqkv, BT, QKVN, CC);
    // 4) scores S^T with causal mask
    scores_kernel<<<dim3(4, NB * NH), 256>>>(fqkv, fwei);
    // 5) softmax over query axis (= rows of S^T)
    softmax_kernel<<<NB * NH, 256>>>(fwei);
    // 6) O = P V
    av_kernel<<<dim3(2, NB * NH), 256>>>(fqkv, fwei, fattn);
    // 7) x1 = x + attn @ w_proj + b_proj
    gemm_kernel<1><<<dim3(CC / 128, BT / 128), 256>>>(fattn, w_proj, b_proj, x,
                                                      fx1, BT, CC, CC);
    // 8) LN2
    ln_kernel<<<BT, 128>>>(fx1, ln2_g, ln2_b, fh);
    // 9) u = relu(h2 @ w1 + b1)
    gemm_kernel<2><<<dim3(C4 / 128, BT / 128), 256>>>(fh, w1, b1, nullptr,
                                                      fu, BT, C4, CC);
    // 10) out = x1 + u @ w2 + b2
    gemm_kernel<1><<<dim3(CC / 128, BT / 128), 256>>>(fu, w2, b2, fx1,
                                                      out, BT, CC, C4);
}

// round 2
// speedup vs baseline: 2.1345x; 2.1345x over previous
#include <cuda_runtime.h>
#include <cstddef>
#include <cstdint>

// Problem constants
#define NB   128          // batch
#define T    256          // sequence
#define CC   384          // embed
#define NH   6            // heads
#define HS   64           // head size
#define C4   1536         // 4*C
#define QKVN 1152         // 3*C
#define BT   32768        // NB*T

// ---------------- scratch (device globals; no allocation allowed) ----------
__device__ float g_h[BT * CC];                       // LN output (reused)
__device__ float g_qkv[(size_t)BT * QKVN];           // q|k|v, (B*T, 1152)
__device__ float g_wei[(size_t)NB * NH * T * T];     // S^T per (b,h): [s][t], then P^T
__device__ float g_attn[BT * CC];                    // attention output
__device__ float g_x1[BT * CC];                      // x after attn sublayer
__device__ float g_u[(size_t)BT * C4];               // MLP hidden
__device__ float g_wpack[CC * QKVN];                 // packed QKV weights (C x 3C)

// ---------------- weight packing: (h,c,d)x3 -> (c, w*384 + h*64 + d) -------
__global__ void pack_kernel(const float* __restrict__ wq,
                            const float* __restrict__ wk,
                            const float* __restrict__ wv,
                            float* __restrict__ wp) {
    int idx = blockIdx.x * 256 + threadIdx.x;
    const int per = NH * CC * HS;                    // 147456
    if (idx >= 3 * per) return;
    int w = idx / per;
    int rem = idx - w * per;                          // (h*C + c)*HS + d
    int d = rem % HS;
    int hc = rem / HS;
    int c = hc % CC;
    int h = hc / CC;
    const float* src = (w == 0) ? wq : (w == 1) ? wk : wv;
    wp[(size_t)c * QKVN + w * CC + h * HS + d] = src[rem];
}

// ---------------- LayerNorm: one block (128 thr) per row --------------------
__global__ void __launch_bounds__(128)
ln_kernel(const float* __restrict__ x, const float* __restrict__ g,
          const float* __restrict__ b, float* __restrict__ out) {
    int row = blockIdx.x;
    const float* xr = x + (size_t)row * CC;
    int t = threadIdx.x;
    float v0 = xr[t], v1 = xr[t + 128], v2 = xr[t + 256];
    float s  = v0 + v1 + v2;
    float ss = v0 * v0 + v1 * v1 + v2 * v2;
    __shared__ float red[8];
    __shared__ float red2[8];
    #pragma unroll
    for (int o = 16; o > 0; o >>= 1) {
        s  += __shfl_down_sync(0xffffffffu, s, o);
        ss += __shfl_down_sync(0xffffffffu, ss, o);
    }
    int warp = t >> 5, lane = t & 31;
    if (lane == 0) { red[warp] = s; red2[warp] = ss; }
    __syncthreads();
    if (t == 0) {
        float S  = red[0] + red[1] + red[2] + red[3];
        float SS = red2[0] + red2[1] + red2[2] + red2[3];
        float mu = S * (1.0f / CC);
        float var = SS * (1.0f / CC) - mu * mu;
        red[4] = mu;
        red2[4] = rsqrtf(var + 1e-5f);
    }
    __syncthreads();
    float mu = red[4], inv = red2[4];
    float* o = out + (size_t)row * CC;
    o[t]       = (v0 - mu) * inv * g[t]       + b[t];
    o[t + 128] = (v1 - mu) * inv * g[t + 128] + b[t + 128];
    o[t + 256] = (v2 - mu) * inv * g[t + 256] + b[t + 256];
}

// ---------------- tf32 helpers ----------------------------------------------
__device__ __forceinline__ uint32_t f2tf32(float f) {
    uint32_t r;
    asm("cvt.rna.tf32.f32 %0, %1;" : "=r"(r) : "f"(f));
    return r;
}

__device__ __forceinline__ void mma_tf32(float* d, const uint32_t* a, const uint32_t* b) {
    asm volatile(
        "mma.sync.aligned.m16n8k8.row.col.f32.tf32.tf32.f32 "
        "{%0,%1,%2,%3}, {%4,%5,%6,%7}, {%8,%9}, {%0,%1,%2,%3};"
        : "+f"(d[0]), "+f"(d[1]), "+f"(d[2]), "+f"(d[3])
        : "r"(a[0]), "r"(a[1]), "r"(a[2]), "r"(a[3]), "r"(b[0]), "r"(b[1]));
}

// ---------------- tensor-core SGEMM (tf32) -----------------------------------
// C = epi(A(MxK,row) * B(KxN,row)); 128x128 tile, BK=16, double-buffered.
// 8 warps in 4(m) x 2(n); warp tile 32x64; m16n8k8 tf32 MMA.
// EPI: 0 = plain, 1 = + bias + residual, 2 = relu(+ bias)
template <int EPI>
__global__ void __launch_bounds__(256, 2)
gemm_tc(const float* __restrict__ A, const float* __restrict__ Bm,
        const float* __restrict__ bias, const float* __restrict__ res,
        float* __restrict__ Cout, int M, int N, int K) {
    __shared__ float As[2][128][20];    // [m][k], pad 20 -> conflict-free frag loads
    __shared__ float Bs[2][16][136];    // [k][n], pad 136 -> conflict-free frag loads

    int tid  = threadIdx.x;
    int m0   = blockIdx.y * 128;
    int n0   = blockIdx.x * 128;
    int warp = tid >> 5, lane = tid & 31;
    int wm = (warp >> 1) * 32;          // warp m offset in tile
    int wn = (warp & 1) * 64;           // warp n offset in tile
    int qid  = lane >> 2;               // groupID   0..7
    int qtid = lane & 3;                // thread-in-group 0..3

    float acc[2][8][4];
    #pragma unroll
    for (int i = 0; i < 2; i++)
        #pragma unroll
        for (int j = 0; j < 8; j++)
            #pragma unroll
            for (int q = 0; q < 4; q++) acc[i][j][q] = 0.0f;

    // gmem load assignments
    int arow = tid >> 2;                // 0..63 (two passes: +0, +64)
    int acol = (tid & 3) * 4;           // 0,4,8,12
    int brow = tid >> 5;                // 0..7 (two passes: +0, +8)
    int bcol = (tid & 31) * 4;

    const float* Ap = A + (size_t)(m0 + arow) * K + acol;
    const float* Bp = Bm + (size_t)brow * N + n0 + bcol;

    uint32_t la[2][4], lb[2][4];
    int KT = K >> 4;

    auto fetch = [&](int kt) {
        #pragma unroll
        for (int i = 0; i < 2; i++) {
            float4 av = *(const float4*)(Ap + (size_t)(i * 64) * K + kt * 16);
            la[i][0] = f2tf32(av.x); la[i][1] = f2tf32(av.y);
            la[i][2] = f2tf32(av.z); la[i][3] = f2tf32(av.w);
            float4 bv = *(const float4*)(Bp + (size_t)(kt * 16 + i * 8) * N);
            lb[i][0] = f2tf32(bv.x); lb[i][1] = f2tf32(bv.y);
            lb[i][2] = f2tf32(bv.z); lb[i][3] = f2tf32(bv.w);
        }
    };
    auto stage = [&](int buf) {
        #pragma unroll
        for (int i = 0; i < 2; i++) {
            *(uint4*)&As[buf][arow + i * 64][acol] = *(uint4*)la[i];
            *(uint4*)&Bs[buf][brow + i * 8][bcol]  = *(uint4*)lb[i];
        }
    };

    fetch(0);
    stage(0);
    __syncthreads();

    int cur = 0;
    for (int kt = 0; kt < KT; kt++) {
        if (kt + 1 < KT) fetch(kt + 1);
        #pragma unroll
        for (int ks = 0; ks < 2; ks++) {
            int kk = ks * 8;
            uint32_t af[2][4], bf[8][2];
            #pragma unroll
            for (int mt = 0; mt < 2; mt++) {
                int r = wm + mt * 16 + qid;
                af[mt][0] = __float_as_uint(As[cur][r][kk + qtid]);
                af[mt][1] = __float_as_uint(As[cur][r + 8][kk + qtid]);
                af[mt][2] = __float_as_uint(As[cur][r][kk + qtid + 4]);
                af[mt][3] = __float_as_uint(As[cur][r + 8][kk + qtid + 4]);
            }
            #pragma unroll
            for (int nt = 0; nt < 8; nt++) {
                int c = wn + nt * 8 + qid;
                bf[nt][0] = __float_as_uint(Bs[cur][kk + qtid][c]);
                bf[nt][1] = __float_as_uint(Bs[cur][kk + qtid + 4][c]);
            }
            #pragma unroll
            for (int mt = 0; mt < 2; mt++)
                #pragma unroll
                for (int nt = 0; nt < 8; nt++)
                    mma_tf32(acc[mt][nt], af[mt], bf[nt]);
        }
        if (kt + 1 < KT) {
            stage(cur ^ 1);
            __syncthreads();
            cur ^= 1;
        }
    }

    // epilogue: each (mt, nt) owns rows {r, r+8}, cols {c, c+1}
    #pragma unroll
    for (int mt = 0; mt < 2; mt++) {
        #pragma unroll
        for (int nt = 0; nt < 8; nt++) {
            int r = m0 + wm + mt * 16 + qid;
            int c = n0 + wn + nt * 8 + 2 * qtid;
            #pragma unroll
            for (int half = 0; half < 2; half++) {
                int rr = r + half * 8;
                float2 v;
                v.x = acc[mt][nt][half * 2 + 0];
                v.y = acc[mt][nt][half * 2 + 1];
                if (EPI == 1) {
                    float2 bb = *(const float2*)(bias + c);
                    float2 rv = *(const float2*)(res + (size_t)rr * N + c);
                    v.x += bb.x + rv.x; v.y += bb.y + rv.y;
                } else if (EPI == 2) {
                    float2 bb = *(const float2*)(bias + c);
                    v.x = fmaxf(v.x + bb.x, 0.0f);
                    v.y = fmaxf(v.y + bb.y, 0.0f);
                }
                *(float2*)(Cout + (size_t)rr * N + c) = v;
            }
        }
    }
}

// ---------------- scores: S^T[s][t] = scale * K[s].Q[t], causal mask -------
__global__ void __launch_bounds__(256)
scores_kernel(const float* __restrict__ qkv, float* __restrict__ wei) {
    int bh = blockIdx.y;
    int b = bh / NH, h = bh % NH;
    int quad = blockIdx.x;
    int s0 = (quad >> 1) * 128;
    int t0 = (quad & 1) * 128;
    int tid = threadIdx.x;
    float* W = wei + (size_t)bh * (T * T);

    if (t0 + 127 < s0) {
        for (int i = tid; i < 128 * 128; i += 256) {
            int s = i >> 7, t = i & 127;
            W[(size_t)(s0 + s) * T + t0 + t] = -1e30f;
        }
        return;
    }

    __shared__ float Ks[8][128];
    __shared__ float Qs[8][128];
    int tx = tid & 15, ty = tid >> 4;
    float acc[8][8];
    #pragma unroll
    for (int i = 0; i < 8; i++)
        #pragma unroll
        for (int j = 0; j < 8; j++) acc[i][j] = 0.0f;

    int arow = tid >> 1;
    int akp  = (tid & 1) * 4;
    const float* Kp = qkv + (size_t)(b * T + s0 + arow) * QKVN + CC + h * HS + akp;
    const float* Qp = qkv + (size_t)(b * T + t0 + arow) * QKVN + 0  + h * HS + akp;

    for (int k0 = 0; k0 < HS; k0 += 8) {
        float4 kv = *(const float4*)(Kp + k0);
        float4 qv = *(const float4*)(Qp + k0);
        Ks[akp + 0][arow] = kv.x; Ks[akp + 1][arow] = kv.y;
        Ks[akp + 2][arow] = kv.z; Ks[akp + 3][arow] = kv.w;
        Qs[akp + 0][arow] = qv.x; Qs[akp + 1][arow] = qv.y;
        Qs[akp + 2][arow] = qv.z; Qs[akp + 3][arow] = qv.w;
        __syncthreads();
        #pragma unroll
        for (int k = 0; k < 8; k++) {
            float a[8], bb[8];
            *(float4*)&a[0]  = *(const float4*)&Ks[k][ty * 4];
            *(float4*)&a[4]  = *(const float4*)&Ks[k][64 + ty * 4];
            *(float4*)&bb[0] = *(const float4*)&Qs[k][tx * 4];
            *(float4*)&bb[4] = *(const float4*)&Qs[k][64 + tx * 4];
            #pragma unroll
            for (int i = 0; i < 8; i++)
                #pragma unroll
                for (int j = 0; j < 8; j++)
                    acc[i][j] = fmaf(a[i], bb[j], acc[i][j]);
        }
        __syncthreads();
    }

    const float scale = 0.05103103630798288f;  // 384^-0.5
    #pragma unroll
    for (int i = 0; i < 8; i++) {
        int s = s0 + ((i < 4) ? (ty * 4 + i) : (64 + ty * 4 + i - 4));
        #pragma unroll
        for (int jj = 0; jj < 2; jj++) {
            int tb = t0 + ((jj == 0) ? (tx * 4) : (64 + tx * 4));
            float4 v;
            float* pv = &v.x;
            #pragma unroll
            for (int q = 0; q < 4; q++) {
                float val = acc[i][jj * 4 + q] * scale;
                pv[q] = (tb + q >= s) ? val : -1e30f;
            }
            *(float4*)(W + (size_t)s * T + tb) = v;
        }
    }
}

// ---------------- column softmax (rows of S^T): warp per row ---------------
__global__ void __launch_bounds__(256)
softmax_kernel(float* __restrict__ wei) {
    int bh = blockIdx.x;
    float* W = wei + (size_t)bh * (T * T);
    int warp = threadIdx.x >> 5, lane = threadIdx.x & 31;
    for (int r = warp; r < T; r += 8) {
        float* row = W + (size_t)r * T;
        float v[8];
        float m = -3e30f;
        #pragma unroll
        for (int j = 0; j < 8; j++) {
            v[j] = row[lane + 32 * j];
            m = fmaxf(m, v[j]);
        }
        #pragma unroll
        for (int o = 16; o > 0; o >>= 1) m = fmaxf(m, __shfl_xor_sync(0xffffffffu, m, o));
        float ssum = 0.0f;
        #pragma unroll
        for (int j = 0; j < 8; j++) {
            v[j] = __expf(v[j] - m);
            ssum += v[j];
        }
        #pragma unroll
        for (int o = 16; o > 0; o >>= 1) ssum += __shfl_xor_sync(0xffffffffu, ssum, o);
        float inv = 1.0f / ssum;
        #pragma unroll
        for (int j = 0; j < 8; j++) row[lane + 32 * j] = v[j] * inv;
    }
}

// ---------------- O[t][d] = sum_s P^T[s][t] * V[s][d]  (TN gemm) -----------
__global__ void __launch_bounds__(256)
av_kernel(const float* __restrict__ qkv, const float* __restrict__ wei,
          float* __restrict__ attn) {
    int bh = blockIdx.y;
    int b = bh / NH, h = bh % NH;
    int t0 = blockIdx.x * 128;
    __shared__ float Ps[16][128];
    __shared__ float Vs[16][64];
    int tid = threadIdx.x;
    int tx = tid & 15, ty = tid >> 4;
    float acc[8][4];
    #pragma unroll
    for (int i = 0; i < 8; i++)
        #pragma unroll
        for (int j = 0; j < 4; j++) acc[i][j] = 0.0f;

    const float* W = wei + (size_t)bh * (T * T);

    for (int s0 = 0; s0 < T; s0 += 16) {
        #pragma unroll
        for (int i = 0; i < 2; i++) {
            int idx = tid + 256 * i;
            int sr = idx >> 5;
            int tc = (idx & 31) * 4;
            *(float4*)&Ps[sr][tc] = *(const float4*)(W + (size_t)(s0 + sr) * T + t0 + tc);
        }
        {
            int sr = tid >> 4;
            int dc = (tid & 15) * 4;
            *(float4*)&Vs[sr][dc] =
                *(const float4*)(qkv + (size_t)(b * T + s0 + sr) * QKVN + 2 * CC + h * HS + dc);
        }
        __syncthreads();
        #pragma unroll
        for (int k = 0; k < 16; k++) {
            float a[8], bb[4];
            *(float4*)&a[0]  = *(const float4*)&Ps[k][ty * 4];
            *(float4*)&a[4]  = *(const float4*)&Ps[k][64 + ty * 4];
            *(float4*)&bb[0] = *(const float4*)&Vs[k][tx * 4];
            #pragma unroll
            for (int i = 0; i < 8; i++)
                #pragma unroll
                for (int j = 0; j < 4; j++)
                    acc[i][j] = fmaf(a[i], bb[j], acc[i][j]);
        }
        __syncthreads();
    }

    #pragma unroll
    for (int i = 0; i < 8; i++) {
        int t = t0 + ((i < 4) ? (ty * 4 + i) : (64 + ty * 4 + i - 4));
        float4 v;
        v.x = acc[i][0]; v.y = acc[i][1]; v.z = acc[i][2]; v.w = acc[i][3];
        *(float4*)(attn + (size_t)(b * T + t) * CC + h * HS + tx * 4) = v;
    }
}

// ---------------- launch ----------------------------------------------------
extern "C" void kernel_launch(void* const* d_in, const int* in_sizes, int n_in,
                              void* d_out, int out_size) {
    (void)in_sizes; (void)n_in; (void)out_size;
    const float* x      = (const float*)d_in[0];
    const float* wq     = (const float*)d_in[1];
    const float* wk     = (const float*)d_in[2];
    const float* wv     = (const float*)d_in[3];
    const float* w_proj = (const float*)d_in[4];
    const float* b_proj = (const float*)d_in[5];
    const float* w1     = (const float*)d_in[6];
    const float* b1     = (const float*)d_in[7];
    const float* w2     = (const float*)d_in[8];
    const float* b2     = (const float*)d_in[9];
    const float* ln1_g  = (const float*)d_in[10];
    const float* ln1_b  = (const float*)d_in[11];
    const float* ln2_g  = (const float*)d_in[12];
    const float* ln2_b  = (const float*)d_in[13];
    float* out = (float*)d_out;

    void *ph, *pqkv, *pwei, *pattn, *px1, *pu, *pwp;
    cudaGetSymbolAddress(&ph,    g_h);
    cudaGetSymbolAddress(&pqkv,  g_qkv);
    cudaGetSymbolAddress(&pwei,  g_wei);
    cudaGetSymbolAddress(&pattn, g_attn);
    cudaGetSymbolAddress(&px1,   g_x1);
    cudaGetSymbolAddress(&pu,    g_u);
    cudaGetSymbolAddress(&pwp,   g_wpack);
    float* fh    = (float*)ph;
    float* fqkv  = (float*)pqkv;
    float* fwei  = (float*)pwei;
    float* fattn = (float*)pattn;
    float* fx1   = (float*)px1;
    float* fu    = (float*)pu;
    float* fwp   = (float*)pwp;

    // 1) pack QKV weights
    pack_kernel<<<(3 * NH * CC * HS + 255) / 256, 256>>>(wq, wk, wv, fwp);
    // 2) LN1
    ln_kernel<<<BT, 128>>>(x, ln1_g, ln1_b, fh);
    // 3) QKV projection: (32768 x 384) @ (384 x 1152)
    gemm_tc<0><<<dim3(QKVN / 128, BT / 128), 256>>>(fh, fwp, nullptr, nullptr,
                                                    fqkv, BT, QKVN, CC);
    // 4) scores S^T with causal mask
    scores_kernel<<<dim3(4, NB * NH), 256>>>(fqkv, fwei);
    // 5) softmax over query axis (= rows of S^T)
    softmax_kernel<<<NB * NH, 256>>>(fwei);
    // 6) O = P V
    av_kernel<<<dim3(2, NB * NH), 256>>>(fqkv, fwei, fattn);
    // 7) x1 = x + attn @ w_proj + b_proj
    gemm_tc<1><<<dim3(CC / 128, BT / 128), 256>>>(fattn, w_proj, b_proj, x,
                                                  fx1, BT, CC, CC);
    // 8) LN2
    ln_kernel<<<BT, 128>>>(fx1, ln2_g, ln2_b, fh);
    // 9) u = relu(h2 @ w1 + b1)
    gemm_tc<2><<<dim3(C4 / 128, BT / 128), 256>>>(fh, w1, b1, nullptr,
                                                  fu, BT, C4, CC);
    // 10) out = x1 + u @ w2 + b2
    gemm_tc<1><<<dim3(CC / 128, BT / 128), 256>>>(fu, w2, b2, fx1,
                                                  out, BT, CC, C4);
}